// round 2
// baseline (speedup 1.0000x reference)
#include <cuda_runtime.h>
#include <math.h>

#define NPART 512
#define NB    16
#define HIDN  100
#define WPB   8            // warps (particles i) per block
#define TPB   256

typedef unsigned long long u64;

__device__ __forceinline__ float ex2f(float x) {
    float y; asm("ex2.approx.ftz.f32 %0, %1;" : "=f"(y) : "f"(x)); return y;
}
__device__ __forceinline__ float rsq_a(float x) {
    float y; asm("rsqrt.approx.ftz.f32 %0, %1;" : "=f"(y) : "f"(x)); return y;
}
__device__ __forceinline__ float rcp_a(float x) {
    float y; asm("rcp.approx.ftz.f32 %0, %1;" : "=f"(y) : "f"(x)); return y;
}

// ---- packed f32x2 helpers (sm_100+ Blackwell) ----
__device__ __forceinline__ u64 pk2(float lo, float hi) {
    u64 d; asm("mov.b64 %0, {%1, %2};" : "=l"(d) : "f"(lo), "f"(hi)); return d;
}
__device__ __forceinline__ void upk2(u64 v, float& lo, float& hi) {
    asm("mov.b64 {%0, %1}, %2;" : "=f"(lo), "=f"(hi) : "l"(v));
}
__device__ __forceinline__ u64 fma2(u64 a, u64 b, u64 c) {
    u64 d; asm("fma.rn.f32x2 %0, %1, %2, %3;" : "=l"(d) : "l"(a), "l"(b), "l"(c)); return d;
}
__device__ __forceinline__ u64 mul2(u64 a, u64 b) {
    u64 d; asm("mul.rn.f32x2 %0, %1, %2;" : "=l"(d) : "l"(a), "l"(b)); return d;
}
__device__ __forceinline__ u64 add2(u64 a, u64 b) {
    u64 d; asm("add.rn.f32x2 %0, %1, %2;" : "=l"(d) : "l"(a), "l"(b)); return d;
}
__device__ __forceinline__ u64 ex2p(u64 a) {
    float lo, hi; upk2(a, lo, hi);
    return pk2(ex2f(lo), ex2f(hi));
}
__device__ __forceinline__ u64 rsqp(u64 a) {
    float lo, hi; upk2(a, lo, hi);
    return pk2(rsq_a(lo), rsq_a(hi));
}

__global__ __launch_bounds__(TPB)
void vortex_fused_kernel(const float* __restrict__ inp,
                         const float* __restrict__ W1,
                         const float* __restrict__ b1,
                         const float* __restrict__ W2,
                         const float* __restrict__ b2,
                         float* __restrict__ out)
{
    // pair-interleaved packed per-j constants; P*[idx] covers j=2*idx, 2*idx+1
    // P0 = { -y pair, -x pair }        P1 = { ml2e pair, mc pair }
    // P2 = { md pair, tau/2pi pair }   P3 = { 1/sig^2 pair, c/2 pair }
    __shared__ ulonglong2 P0[NPART / 2], P1[NPART / 2], P2[NPART / 2], P3[NPART / 2];
    // scalar per-particle data for the feature vector / epilogue
    __shared__ float sy[NPART], sx[NPART], stau[NPART], ssig[NPART];
    __shared__ float sc[NPART], sd[NPART];
    // MLP weights
    __shared__ float sW1[10 * HIDN], sb1[HIDN], sW2[HIDN * 6], sb2v[6];

    const int tid  = threadIdx.x;
    const int bpb  = NPART / WPB;              // 64 blocks per batch
    const int b    = blockIdx.x / bpb;
    const int ig   = blockIdx.x % bpb;
    const int warp = tid >> 5;
    const int lane = tid & 31;
    const int i    = ig * WPB + warp;

    const float L2E    = 1.4426950408889634f;
    const float LN2    = 0.6931471805599453f;
    const float INV2PI = 0.15915494309189535f;

    // ---- cooperative load + per-particle precompute ----
    const float* binp = inp + (size_t)b * NPART * 6;
    float* f0 = (float*)P0; float* f1 = (float*)P1;
    float* f2 = (float*)P2; float* f3 = (float*)P3;
    for (int p = tid; p < NPART; p += TPB) {
        float y   = binp[p * 6 + 0];
        float x   = binp[p * 6 + 1];
        float tau = binp[p * 6 + 2];
        float sig = binp[p * 6 + 3];
        float c   = binp[p * 6 + 4];
        float d   = binp[p * 6 + 5];
        sy[p] = y;  sx[p] = x;  stau[p] = tau; ssig[p] = sig;
        sc[p] = c;  sd[p] = d;
        float is2 = rcp_a(sig * sig);
        int idx = p >> 1, o = p & 1;
        f0[idx * 4 + 0 + o] = -y;
        f0[idx * 4 + 2 + o] = -x;
        f1[idx * 4 + 0 + o] = -is2 * L2E;   // ml2e
        f1[idx * 4 + 2 + o] = -c * L2E;     // mc
        f2[idx * 4 + 0 + o] = -d * L2E;     // md
        f2[idx * 4 + 2 + o] = tau * INV2PI; // t2p
        f3[idx * 4 + 0 + o] = is2;
        f3[idx * 4 + 2 + o] = 0.5f * c;     // hc
    }
    for (int p = tid; p < 10 * HIDN; p += TPB) sW1[p] = W1[p];
    for (int p = tid; p < HIDN;      p += TPB) sb1[p] = b1[p];
    for (int p = tid; p < HIDN * 6;  p += TPB) sW2[p] = W2[p];
    if (tid < 6) sb2v[tid] = b2[tid];
    __syncthreads();

    // ---- all-pairs mainloop: one warp per i, lanes handle packed j-pairs ----
    const float yi = sy[i], xi = sx[i];
    const u64 yi2  = pk2(yi, yi);
    const u64 xi2  = pk2(xi, xi);
    const u64 ones = pk2(1.0f, 1.0f);
    const u64 nones = pk2(-1.0f, -1.0f);
    const u64 eps2 = pk2(1e-6f, 1e-6f);
    const u64 nln2 = pk2(-LN2, -LN2);

    u64 aSvy = 0ull, aSvx = 0ull, aSF = 0ull;
    u64 aSG = 0ull, aSGxx = 0ull, aSGyy = 0ull;

    #pragma unroll 4
    for (int jj = 0; jj < NPART / 64; ++jj) {
        int idx = jj * 32 + lane;
        ulonglong2 q0 = P0[idx];
        ulonglong2 q1 = P1[idx];
        ulonglong2 q2 = P2[idx];
        ulonglong2 q3 = P3[idx];

        u64 dy  = add2(yi2, q0.x);                 // yi - yj
        u64 dx  = add2(xi2, q0.y);                 // xi - xj
        u64 sq  = fma2(dy, dy, mul2(dx, dx));
        u64 s   = add2(sq, eps2);
        u64 rs  = rsqp(s);                         // 1/sqrt(s)
        u64 r   = mul2(s, rs);                     // sqrt(s)
        u64 ivs = mul2(rs, rs);                    // 1/s
        u64 e1  = ex2p(mul2(sq, q1.x));            // exp(-sq/sig^2)
        u64 e2  = ex2p(fma2(q1.y, r, mul2(q2.x, sq))); // exp(-c r - d sq)
        u64 g   = fma2(e1, nones, ones);           // 1 - e1 (== 0 for j==i)
        u64 gh  = mul2(g, e2);
        u64 A   = mul2(q2.y, ivs);                 // tau/(2 pi s)
        u64 F   = mul2(A, gh);
        u64 Fn  = mul2(F, nones);
        u64 t1  = mul2(mul2(q3.x, e1), e2);        // g' h
        u64 At1 = mul2(A, t1);
        u64 dd  = mul2(q2.x, nln2);                // d = -md*ln2
        u64 t2  = fma2(q3.y, rs, add2(dd, ivs));   // c/(2r) + d + 1/s
        u64 Fp  = fma2(Fn, t2, At1);               // A*(t1 - gh*t2)
        u64 G2  = add2(Fp, Fp);
        aSvy  = fma2(Fn, dx, aSvy);
        aSvx  = fma2(F,  dy, aSvx);
        aSF   = add2(aSF, F);
        u64 gdy = mul2(G2, dy);
        u64 gdx = mul2(G2, dx);
        aSG   = fma2(gdy, dx, aSG);
        aSGxx = fma2(gdx, dx, aSGxx);
        aSGyy = fma2(gdy, dy, aSGyy);
    }

    // ---- horizontal add of packed halves, then warp butterfly reduce ----
    float l0, h0; float Svy, Svx, SF, SG, SGxx, SGyy;
    upk2(aSvy,  l0, h0); Svy  = l0 + h0;
    upk2(aSvx,  l0, h0); Svx  = l0 + h0;
    upk2(aSF,   l0, h0); SF   = l0 + h0;
    upk2(aSG,   l0, h0); SG   = l0 + h0;
    upk2(aSGxx, l0, h0); SGxx = l0 + h0;
    upk2(aSGyy, l0, h0); SGyy = l0 + h0;

    #pragma unroll
    for (int o = 16; o; o >>= 1) {
        Svy  += __shfl_xor_sync(0xffffffffu, Svy,  o);
        Svx  += __shfl_xor_sync(0xffffffffu, Svx,  o);
        SF   += __shfl_xor_sync(0xffffffffu, SF,   o);
        SG   += __shfl_xor_sync(0xffffffffu, SG,   o);
        SGxx += __shfl_xor_sync(0xffffffffu, SGxx, o);
        SGyy += __shfl_xor_sync(0xffffffffu, SGyy, o);
    }

    // feature vector: tau, sig, c, d, vy, vx, dvy/dy, dvy/dx, dvx/dy, dvx/dx
    float feat[10];
    feat[0] = stau[i]; feat[1] = ssig[i]; feat[2] = sc[i]; feat[3] = sd[i];
    feat[4] = Svy;     feat[5] = Svx;
    feat[6] = -SG;             // dvy/dy
    feat[7] = -(SGxx + SF);    // dvy/dx
    feat[8] = SGyy + SF;       // dvx/dy
    feat[9] = SG;              // dvx/dx = -dvy/dy

    // ---- MLP 10 -> 100 (LeakyReLU 0.1) -> 6, lanes own hidden units ----
    float po[6] = {0.f, 0.f, 0.f, 0.f, 0.f, 0.f};
    #pragma unroll
    for (int rblk = 0; rblk < 4; ++rblk) {
        int k = rblk * 32 + lane;
        if (k < HIDN) {
            float h = sb1[k];
            #pragma unroll
            for (int f = 0; f < 10; ++f) h = fmaf(feat[f], sW1[f * HIDN + k], h);
            h = (h >= 0.0f) ? h : 0.1f * h;
            #pragma unroll
            for (int m = 0; m < 6; ++m) po[m] = fmaf(h, sW2[k * 6 + m], po[m]);
        }
    }
    #pragma unroll
    for (int o = 16; o; o >>= 1) {
        #pragma unroll
        for (int m = 0; m < 6; ++m)
            po[m] += __shfl_xor_sync(0xffffffffu, po[m], o);
    }

    // ---- epilogue ----
    if (lane == 0) {
        float o0 = po[0] + sb2v[0];
        float o1 = po[1] + sb2v[1];
        float o2 = po[2] + sb2v[2];
        float o3 = po[3] + sb2v[3];
        float o4 = po[4] + sb2v[4];
        float o5 = po[5] + sb2v[5];
        float* op = out + ((size_t)b * NPART + i) * 6;
        op[0] = yi      + 0.1f * o0;
        op[1] = xi      + 0.1f * o1;
        op[2] = feat[0] + 0.1f * o2;
        op[3] = feat[1] + 0.1f * o3;
        // numerically-stable softplus, matching jax.nn.softplus
        float sp4 = fmaxf(o4, 0.0f) + log1pf(expf(-fabsf(o4)));
        float sp5 = fmaxf(o5, 0.0f) + log1pf(expf(-fabsf(o5)));
        op[4] = 0.1f * sp4;
        op[5] = 0.1f * sp5;
    }
}

extern "C" void kernel_launch(void* const* d_in, const int* in_sizes, int n_in,
                              void* d_out, int out_size)
{
    const float* inp = (const float*)d_in[0];  // (16,512,6)
    const float* W1  = (const float*)d_in[1];  // (10,100)
    const float* b1  = (const float*)d_in[2];  // (100,)
    const float* W2  = (const float*)d_in[3];  // (100,6)
    const float* b2  = (const float*)d_in[4];  // (6,)
    float* out = (float*)d_out;                // (16,512,6)

    dim3 grid(NB * (NPART / WPB));             // 1024 blocks
    dim3 block(TPB);                           // 8 warps: 1 warp per particle i
    vortex_fused_kernel<<<grid, block>>>(inp, W1, b1, W2, b2, out);
}

// round 3
// speedup vs baseline: 1.1423x; 1.1423x over previous
#include <cuda_runtime.h>
#include <math.h>

#define NPART 512
#define NB    16
#define HIDN  100
#define WPB   8            // warps per block
#define NI    2            // particles i per warp
#define TPB   256

typedef unsigned long long u64;

__device__ __forceinline__ float ex2f(float x) {
    float y; asm("ex2.approx.ftz.f32 %0, %1;" : "=f"(y) : "f"(x)); return y;
}
__device__ __forceinline__ float rsq_a(float x) {
    float y; asm("rsqrt.approx.ftz.f32 %0, %1;" : "=f"(y) : "f"(x)); return y;
}
__device__ __forceinline__ float rcp_a(float x) {
    float y; asm("rcp.approx.ftz.f32 %0, %1;" : "=f"(y) : "f"(x)); return y;
}

// ---- packed f32x2 helpers (sm_100+) ----
__device__ __forceinline__ u64 pk2(float lo, float hi) {
    u64 d; asm("mov.b64 %0, {%1, %2};" : "=l"(d) : "f"(lo), "f"(hi)); return d;
}
__device__ __forceinline__ void upk2(u64 v, float& lo, float& hi) {
    asm("mov.b64 {%0, %1}, %2;" : "=f"(lo), "=f"(hi) : "l"(v));
}
__device__ __forceinline__ u64 fma2(u64 a, u64 b, u64 c) {
    u64 d; asm("fma.rn.f32x2 %0, %1, %2, %3;" : "=l"(d) : "l"(a), "l"(b), "l"(c)); return d;
}
__device__ __forceinline__ u64 mul2(u64 a, u64 b) {
    u64 d; asm("mul.rn.f32x2 %0, %1, %2;" : "=l"(d) : "l"(a), "l"(b)); return d;
}
__device__ __forceinline__ u64 add2(u64 a, u64 b) {
    u64 d; asm("add.rn.f32x2 %0, %1, %2;" : "=l"(d) : "l"(a), "l"(b)); return d;
}
__device__ __forceinline__ u64 ex2p(u64 a) {
    float lo, hi; upk2(a, lo, hi);
    return pk2(ex2f(lo), ex2f(hi));
}
__device__ __forceinline__ u64 rsqp(u64 a) {
    float lo, hi; upk2(a, lo, hi);
    return pk2(rsq_a(lo), rsq_a(hi));
}

struct Acc { u64 vy, vx, F, G, Gxx, Gyy; };

// per-pair vortex interaction for one query point (packed 2 j's)
__device__ __forceinline__ void pair_body(
    u64 yi2, u64 xi2, const ulonglong2& q0, const ulonglong2& q1,
    const ulonglong2& q2, const ulonglong2& q3, u64 dd, Acc& a,
    u64 ones, u64 nones, u64 eps2)
{
    u64 dy  = add2(yi2, q0.x);                 // yi - yj
    u64 dx  = add2(xi2, q0.y);                 // xi - xj
    u64 sq  = fma2(dy, dy, mul2(dx, dx));
    u64 s   = add2(sq, eps2);
    u64 rs  = rsqp(s);                         // 1/sqrt(s)
    u64 r   = mul2(s, rs);                     // sqrt(s)
    u64 ivs = mul2(rs, rs);                    // 1/s
    u64 e1  = ex2p(mul2(sq, q1.x));            // exp(-sq/sig^2)
    u64 e2  = ex2p(fma2(q1.y, r, mul2(q2.x, sq))); // exp(-c r - d sq)
    u64 g   = fma2(e1, nones, ones);           // 1 - e1 (== 0 for j==i)
    u64 gh  = mul2(g, e2);
    u64 A   = mul2(q2.y, ivs);                 // tau/(2 pi s)
    u64 F   = mul2(A, gh);
    u64 Fn  = mul2(F, nones);
    u64 t1  = mul2(mul2(q3.x, e1), e2);        // g' h
    u64 At1 = mul2(A, t1);
    u64 t2  = fma2(q3.y, rs, add2(dd, ivs));   // c/(2r) + d + 1/s
    u64 Fp  = fma2(Fn, t2, At1);               // A*(t1 - gh*t2)
    u64 G2  = add2(Fp, Fp);
    a.vy  = fma2(Fn, dx, a.vy);
    a.vx  = fma2(F,  dy, a.vx);
    a.F   = add2(a.F, F);
    u64 gdy = mul2(G2, dy);
    u64 gdx = mul2(G2, dx);
    a.G   = fma2(gdy, dx, a.G);
    a.Gxx = fma2(gdx, dx, a.Gxx);
    a.Gyy = fma2(gdy, dy, a.Gyy);
}

__global__ __launch_bounds__(TPB)
void vortex_fused_kernel(const float* __restrict__ inp,
                         const float* __restrict__ W1,
                         const float* __restrict__ b1,
                         const float* __restrict__ W2,
                         const float* __restrict__ b2,
                         float* __restrict__ out)
{
    // pair-interleaved packed per-j constants; P*[idx] covers j=2*idx, 2*idx+1
    // P0 = { -y pair, -x pair }        P1 = { ml2e pair, mc pair }
    // P2 = { md pair, tau/2pi pair }   P3 = { 1/sig^2 pair, c/2 pair }
    __shared__ ulonglong2 P0[NPART / 2], P1[NPART / 2], P2[NPART / 2], P3[NPART / 2];
    __shared__ float sy[NPART], sx[NPART], stau[NPART], ssig[NPART];
    __shared__ float sc[NPART], sd[NPART];
    // MLP weights; sW2T is transposed: sW2T[m*HIDN + k] = W2[k*6 + m]
    __shared__ float sW1[10 * HIDN], sb1[HIDN], sW2T[6 * HIDN], sb2v[6];

    const int tid  = threadIdx.x;
    const int ipb  = WPB * NI;                 // 16 i's per block
    const int bpb  = NPART / ipb;              // 32 blocks per batch
    const int b    = blockIdx.x / bpb;
    const int ig   = blockIdx.x % bpb;
    const int warp = tid >> 5;
    const int lane = tid & 31;
    const int i0   = ig * ipb + warp * NI;     // this warp's first particle
    const int i1   = i0 + 1;

    const float L2E    = 1.4426950408889634f;
    const float LN2    = 0.6931471805599453f;
    const float INV2PI = 0.15915494309189535f;

    // ---- cooperative load + per-particle precompute ----
    const float* binp = inp + (size_t)b * NPART * 6;
    float* f0 = (float*)P0; float* f1 = (float*)P1;
    float* f2 = (float*)P2; float* f3 = (float*)P3;
    for (int p = tid; p < NPART; p += TPB) {
        float y   = binp[p * 6 + 0];
        float x   = binp[p * 6 + 1];
        float tau = binp[p * 6 + 2];
        float sig = binp[p * 6 + 3];
        float c   = binp[p * 6 + 4];
        float d   = binp[p * 6 + 5];
        sy[p] = y;  sx[p] = x;  stau[p] = tau; ssig[p] = sig;
        sc[p] = c;  sd[p] = d;
        float is2 = rcp_a(sig * sig);
        int idx = p >> 1, o = p & 1;
        f0[idx * 4 + 0 + o] = -y;
        f0[idx * 4 + 2 + o] = -x;
        f1[idx * 4 + 0 + o] = -is2 * L2E;   // ml2e
        f1[idx * 4 + 2 + o] = -c * L2E;     // mc
        f2[idx * 4 + 0 + o] = -d * L2E;     // md
        f2[idx * 4 + 2 + o] = tau * INV2PI; // t2p
        f3[idx * 4 + 0 + o] = is2;
        f3[idx * 4 + 2 + o] = 0.5f * c;     // hc
    }
    for (int p = tid; p < 10 * HIDN; p += TPB) sW1[p] = W1[p];
    for (int p = tid; p < HIDN;      p += TPB) sb1[p] = b1[p];
    for (int p = tid; p < HIDN * 6;  p += TPB) {
        int k = p / 6, m = p % 6;
        sW2T[m * HIDN + k] = W2[p];
    }
    if (tid < 6) sb2v[tid] = b2[tid];
    __syncthreads();

    // ---- all-pairs mainloop: one warp per 2 i's, lanes handle packed j-pairs ----
    const float yiA = sy[i0], xiA = sx[i0];
    const float yiB = sy[i1], xiB = sx[i1];
    const u64 yA = pk2(yiA, yiA), xA = pk2(xiA, xiA);
    const u64 yB = pk2(yiB, yiB), xB = pk2(xiB, xiB);
    const u64 ones  = pk2(1.0f, 1.0f);
    const u64 nones = pk2(-1.0f, -1.0f);
    const u64 eps2  = pk2(1e-6f, 1e-6f);
    const u64 nln2  = pk2(-LN2, -LN2);

    Acc accA = {0,0,0,0,0,0};
    Acc accB = {0,0,0,0,0,0};

    #pragma unroll 2
    for (int jj = 0; jj < NPART / 64; ++jj) {
        int idx = jj * 32 + lane;
        ulonglong2 q0 = P0[idx];
        ulonglong2 q1 = P1[idx];
        ulonglong2 q2 = P2[idx];
        ulonglong2 q3 = P3[idx];
        u64 dd = mul2(q2.x, nln2);             // d = -md*ln2 (shared)
        pair_body(yA, xA, q0, q1, q2, q3, dd, accA, ones, nones, eps2);
        pair_body(yB, xB, q0, q1, q2, q3, dd, accB, ones, nones, eps2);
    }

    // ---- horizontal add of packed halves, then warp butterfly reduce ----
    float red[12];
    {
        float l, h;
        upk2(accA.vy,  l, h); red[0]  = l + h;
        upk2(accA.vx,  l, h); red[1]  = l + h;
        upk2(accA.F,   l, h); red[2]  = l + h;
        upk2(accA.G,   l, h); red[3]  = l + h;
        upk2(accA.Gxx, l, h); red[4]  = l + h;
        upk2(accA.Gyy, l, h); red[5]  = l + h;
        upk2(accB.vy,  l, h); red[6]  = l + h;
        upk2(accB.vx,  l, h); red[7]  = l + h;
        upk2(accB.F,   l, h); red[8]  = l + h;
        upk2(accB.G,   l, h); red[9]  = l + h;
        upk2(accB.Gxx, l, h); red[10] = l + h;
        upk2(accB.Gyy, l, h); red[11] = l + h;
    }
    #pragma unroll
    for (int o = 16; o; o >>= 1) {
        #pragma unroll
        for (int m = 0; m < 12; ++m)
            red[m] += __shfl_xor_sync(0xffffffffu, red[m], o);
    }

    // feature vectors: tau, sig, c, d, vy, vx, dvy/dy, dvy/dx, dvx/dy, dvx/dx
    float featA[10], featB[10];
    featA[0] = stau[i0]; featA[1] = ssig[i0]; featA[2] = sc[i0]; featA[3] = sd[i0];
    featA[4] = red[0];   featA[5] = red[1];
    featA[6] = -red[3];            // dvy/dy
    featA[7] = -(red[4] + red[2]); // dvy/dx
    featA[8] = red[5] + red[2];    // dvx/dy
    featA[9] = red[3];             // dvx/dx
    featB[0] = stau[i1]; featB[1] = ssig[i1]; featB[2] = sc[i1]; featB[3] = sd[i1];
    featB[4] = red[6];   featB[5] = red[7];
    featB[6] = -red[9];
    featB[7] = -(red[10] + red[8]);
    featB[8] = red[11] + red[8];
    featB[9] = red[9];

    // ---- MLP 10 -> 100 (LeakyReLU 0.1) -> 6, fused over both i's ----
    float poA[6] = {0,0,0,0,0,0};
    float poB[6] = {0,0,0,0,0,0};
    #pragma unroll
    for (int rblk = 0; rblk < 4; ++rblk) {
        int k = rblk * 32 + lane;
        if (k < HIDN) {
            float hA = sb1[k];
            float hB = hA;
            #pragma unroll
            for (int f = 0; f < 10; ++f) {
                float w = sW1[f * HIDN + k];       // shared between A and B
                hA = fmaf(featA[f], w, hA);
                hB = fmaf(featB[f], w, hB);
            }
            hA = (hA >= 0.0f) ? hA : 0.1f * hA;
            hB = (hB >= 0.0f) ? hB : 0.1f * hB;
            #pragma unroll
            for (int m = 0; m < 6; ++m) {
                float w = sW2T[m * HIDN + k];      // 1 wavefront per LDS
                poA[m] = fmaf(hA, w, poA[m]);
                poB[m] = fmaf(hB, w, poB[m]);
            }
        }
    }
    #pragma unroll
    for (int o = 16; o; o >>= 1) {
        #pragma unroll
        for (int m = 0; m < 6; ++m) {
            poA[m] += __shfl_xor_sync(0xffffffffu, poA[m], o);
            poB[m] += __shfl_xor_sync(0xffffffffu, poB[m], o);
        }
    }

    // ---- epilogue (lane 0 writes both particles) ----
    if (lane == 0) {
        float* opA = out + ((size_t)b * NPART + i0) * 6;
        float oA[6];
        #pragma unroll
        for (int m = 0; m < 6; ++m) oA[m] = poA[m] + sb2v[m];
        opA[0] = yiA      + 0.1f * oA[0];
        opA[1] = xiA      + 0.1f * oA[1];
        opA[2] = featA[0] + 0.1f * oA[2];
        opA[3] = featA[1] + 0.1f * oA[3];
        float sp4 = fmaxf(oA[4], 0.0f) + log1pf(expf(-fabsf(oA[4])));
        float sp5 = fmaxf(oA[5], 0.0f) + log1pf(expf(-fabsf(oA[5])));
        opA[4] = 0.1f * sp4;
        opA[5] = 0.1f * sp5;

        float* opB = out + ((size_t)b * NPART + i1) * 6;
        float oB[6];
        #pragma unroll
        for (int m = 0; m < 6; ++m) oB[m] = poB[m] + sb2v[m];
        opB[0] = yiB      + 0.1f * oB[0];
        opB[1] = xiB      + 0.1f * oB[1];
        opB[2] = featB[0] + 0.1f * oB[2];
        opB[3] = featB[1] + 0.1f * oB[3];
        float sq4 = fmaxf(oB[4], 0.0f) + log1pf(expf(-fabsf(oB[4])));
        float sq5 = fmaxf(oB[5], 0.0f) + log1pf(expf(-fabsf(oB[5])));
        opB[4] = 0.1f * sq4;
        opB[5] = 0.1f * sq5;
    }
}

extern "C" void kernel_launch(void* const* d_in, const int* in_sizes, int n_in,
                              void* d_out, int out_size)
{
    const float* inp = (const float*)d_in[0];  // (16,512,6)
    const float* W1  = (const float*)d_in[1];  // (10,100)
    const float* b1  = (const float*)d_in[2];  // (100,)
    const float* W2  = (const float*)d_in[3];  // (100,6)
    const float* b2  = (const float*)d_in[4];  // (6,)
    float* out = (float*)d_out;                // (16,512,6)

    dim3 grid(NB * (NPART / (WPB * NI)));      // 512 blocks
    dim3 block(TPB);
    vortex_fused_kernel<<<grid, block>>>(inp, W1, b1, W2, b2, out);
}